// round 1
// baseline (speedup 1.0000x reference)
#include <cuda_runtime.h>
#include <math.h>

// Problem constants
#define B_   64
#define IN_  512
#define M_   1024
#define NG   6          // q,k,v,i,f,o
// gate scratch layout: [gate][b][m]
__device__ float g_gates[NG * B_ * M_];
__device__ float g_htilde[B_ * M_];

// ---------------------------------------------------------------------------
// Kernel 1: fused 6-gate GEMM  out[g,b,n] = act_g( x[b,:] . W_g[n,:] + bias_g[n] )
// Block tile: BM=64 (all batches) x BN=64, BK=32. 256 threads, 4x4 microtile.
// grid.x = 6144/64 = 96 blocks; each block lies entirely within one gate.
// ---------------------------------------------------------------------------
__global__ __launch_bounds__(256)
void gates_gemm(const float* __restrict__ x,
                const float* __restrict__ Wq, const float* __restrict__ bq,
                const float* __restrict__ Wk, const float* __restrict__ bk,
                const float* __restrict__ Wv, const float* __restrict__ bv,
                const float* __restrict__ Wi, const float* __restrict__ bi,
                const float* __restrict__ Wf, const float* __restrict__ bf,
                const float* __restrict__ Wo, const float* __restrict__ bo)
{
    const int n_global0 = blockIdx.x * 64;          // [0, 6144)
    const int gate      = n_global0 >> 10;          // 0..5
    const int n_local0  = n_global0 & (M_ - 1);     // within-gate column base

    const float* W; const float* bias;
    switch (gate) {
        case 0: W = Wq; bias = bq; break;
        case 1: W = Wk; bias = bk; break;
        case 2: W = Wv; bias = bv; break;
        case 3: W = Wi; bias = bi; break;
        case 4: W = Wf; bias = bf; break;
        default: W = Wo; bias = bo; break;
    }

    __shared__ float As[64][33];   // x tile   [b][k]
    __shared__ float Bs[64][33];   // W tile   [n][k]

    const int tid = threadIdx.x;
    const int tx = tid & 15;       // n direction (16)
    const int ty = tid >> 4;       // b direction (16)

    float acc[4][4];
    #pragma unroll
    for (int r = 0; r < 4; r++)
        #pragma unroll
        for (int c = 0; c < 4; c++) acc[r][c] = 0.f;

    for (int k0 = 0; k0 < IN_; k0 += 32) {
        // cooperative load: 2048 floats each tile, 8 per thread, coalesced
        #pragma unroll
        for (int i = 0; i < 8; i++) {
            int l   = tid + i * 256;       // [0,2048)
            int row = l >> 5;
            int kk  = l & 31;
            As[row][kk] = x[row * IN_ + k0 + kk];
            Bs[row][kk] = W[(n_local0 + row) * IN_ + k0 + kk];
        }
        __syncthreads();

        #pragma unroll
        for (int kk = 0; kk < 32; kk++) {
            float a[4], bb[4];
            #pragma unroll
            for (int r = 0; r < 4; r++) a[r]  = As[ty * 4 + r][kk];
            #pragma unroll
            for (int c = 0; c < 4; c++) bb[c] = Bs[tx * 4 + c][kk];
            #pragma unroll
            for (int r = 0; r < 4; r++)
                #pragma unroll
                for (int c = 0; c < 4; c++) acc[r][c] = fmaf(a[r], bb[c], acc[r][c]);
        }
        __syncthreads();
    }

    // epilogue: bias + activation, write to scratch
    float* out = g_gates + gate * (B_ * M_);
    #pragma unroll
    for (int c = 0; c < 4; c++) {
        int n = n_local0 + tx * 4 + c;
        float bv_ = bias[n];
        #pragma unroll
        for (int r = 0; r < 4; r++) {
            int b = ty * 4 + r;
            float v = acc[r][c] + bv_;
            if (gate == 1)      v *= 0.03125f;                 // 1/sqrt(1024)
            else if (gate == 3) v = __expf(v);                 // i: exp
            else if (gate >= 4) v = 1.f / (1.f + __expf(-v));  // f,o: sigmoid
            out[b * M_ + n] = v;
        }
    }
}

// ---------------------------------------------------------------------------
// Kernel 2: C_t[b,m,:] = f[b,m]*C_prev[b,m,:] + (i*v)[b,m]*k[b,:]
//           h_tilde[b,m] = C_t[b,m,:] . q[b,:]     (fused, warp-reduced)
// grid = (16, 64): blockIdx.y = batch, blockIdx.x = 64-row chunk.
// 256 threads = 8 warps; warp owns one row per iteration (8 iterations).
// ---------------------------------------------------------------------------
__global__ __launch_bounds__(256)
void update_C(const float* __restrict__ Cprev, float* __restrict__ Cout)
{
    const int b = blockIdx.y;
    __shared__ float sk[M_];
    __shared__ float sq[M_];

    const float* gq = g_gates + 0 * (B_ * M_) + b * M_;
    const float* gk = g_gates + 1 * (B_ * M_) + b * M_;
    // stage k and q in smem (256 float4 each, one per thread)
    ((float4*)sk)[threadIdx.x] = ((const float4*)gk)[threadIdx.x];
    ((float4*)sq)[threadIdx.x] = ((const float4*)gq)[threadIdx.x];
    __syncthreads();

    const int warp = threadIdx.x >> 5;
    const int lane = threadIdx.x & 31;
    const float* gv = g_gates + 2 * (B_ * M_) + b * M_;
    const float* gi = g_gates + 3 * (B_ * M_) + b * M_;
    const float* gf = g_gates + 4 * (B_ * M_) + b * M_;

    #pragma unroll
    for (int r = 0; r < 8; r++) {
        const int m = blockIdx.x * 64 + r * 8 + warp;
        const float fm = gf[m];
        const float cm = gi[m] * gv[m];

        const float4* cp = (const float4*)(Cprev + ((size_t)b * M_ + m) * M_);
        float4*       co = (float4*)(Cout  + ((size_t)b * M_ + m) * M_);

        float dot = 0.f;
        #pragma unroll
        for (int it = 0; it < 8; it++) {
            const int n4 = it * 32 + lane;
            float4 c  = cp[n4];
            float4 kk = ((const float4*)sk)[n4];
            float4 qq = ((const float4*)sq)[n4];
            float4 o;
            o.x = fmaf(fm, c.x, cm * kk.x);
            o.y = fmaf(fm, c.y, cm * kk.y);
            o.z = fmaf(fm, c.z, cm * kk.z);
            o.w = fmaf(fm, c.w, cm * kk.w);
            co[n4] = o;
            dot = fmaf(o.x, qq.x, dot);
            dot = fmaf(o.y, qq.y, dot);
            dot = fmaf(o.z, qq.z, dot);
            dot = fmaf(o.w, qq.w, dot);
        }
        #pragma unroll
        for (int off = 16; off; off >>= 1)
            dot += __shfl_xor_sync(0xffffffffu, dot, off);
        if (lane == 0) g_htilde[b * M_ + m] = dot;
    }
}

// ---------------------------------------------------------------------------
// Kernel 3: n_t = f*n_prev + i*k ; denom = max(n_t.q, 1) ; h_t = o*h_tilde/denom
// One block per batch, 256 threads, 4 elements each.
// ---------------------------------------------------------------------------
__global__ __launch_bounds__(256)
void finalize(const float* __restrict__ nprev,
              float* __restrict__ out_h, float* __restrict__ out_n)
{
    const int b   = blockIdx.x;
    const int tid = threadIdx.x;

    const float* gq = g_gates + 0 * (B_ * M_) + b * M_;
    const float* gk = g_gates + 1 * (B_ * M_) + b * M_;
    const float* gi = g_gates + 3 * (B_ * M_) + b * M_;
    const float* gf = g_gates + 4 * (B_ * M_) + b * M_;
    const float* go = g_gates + 5 * (B_ * M_) + b * M_;

    float part = 0.f;
    #pragma unroll
    for (int r = 0; r < 4; r++) {
        int j = tid + r * 256;
        float n = fmaf(gf[j], nprev[b * M_ + j], gi[j] * gk[j]);
        out_n[b * M_ + j] = n;
        part = fmaf(n, gq[j], part);
    }

    __shared__ float red[256];
    red[tid] = part;
    __syncthreads();
    #pragma unroll
    for (int s = 128; s > 0; s >>= 1) {
        if (tid < s) red[tid] += red[tid + s];
        __syncthreads();
    }
    const float denom = fmaxf(red[0], 1.0f);
    const float inv   = 1.0f / denom;

    #pragma unroll
    for (int r = 0; r < 4; r++) {
        int j = tid + r * 256;
        out_h[b * M_ + j] = go[j] * g_htilde[b * M_ + j] * inv;
    }
}

// ---------------------------------------------------------------------------
// Launch. Inputs (metadata order):
// 0 x, 1 h_prev, 2 c_prev, 3 C_prev, 4 n_prev, 5 m_prev,
// 6 Wq, 7 bq, 8 Wk, 9 bk, 10 Wv, 11 bv, 12 Wi, 13 bi, 14 Wf, 15 bf, 16 Wo, 17 bo
// Output: concat(h_t [64*1024], C_t [64*1024*1024], n_t [64*1024])
// ---------------------------------------------------------------------------
extern "C" void kernel_launch(void* const* d_in, const int* in_sizes, int n_in,
                              void* d_out, int out_size)
{
    const float* x     = (const float*)d_in[0];
    const float* Cprev = (const float*)d_in[3];
    const float* nprev = (const float*)d_in[4];

    const float* Wq = (const float*)d_in[6];  const float* bq = (const float*)d_in[7];
    const float* Wk = (const float*)d_in[8];  const float* bk = (const float*)d_in[9];
    const float* Wv = (const float*)d_in[10]; const float* bv = (const float*)d_in[11];
    const float* Wi = (const float*)d_in[12]; const float* bi = (const float*)d_in[13];
    const float* Wf = (const float*)d_in[14]; const float* bf = (const float*)d_in[15];
    const float* Wo = (const float*)d_in[16]; const float* bo = (const float*)d_in[17];

    float* out   = (float*)d_out;
    float* out_h = out;                                    // [64*1024]
    float* out_C = out + (size_t)B_ * M_;                  // [64*1024*1024]
    float* out_n = out + (size_t)B_ * M_ + (size_t)B_ * M_ * M_;

    gates_gemm<<<96, 256>>>(x, Wq, bq, Wk, bk, Wv, bv, Wi, bi, Wf, bf, Wo, bo);

    dim3 grid2(16, 64);
    update_C<<<grid2, 256>>>(Cprev, out_C);

    finalize<<<B_, 256>>>(nprev, out_h, out_n);
}

// round 2
// speedup vs baseline: 1.0977x; 1.0977x over previous
#include <cuda_runtime.h>
#include <math.h>

// Problem constants
#define B_   64
#define IN_  512
#define M_   1024
#define NG   6          // q,k,v,i,f,o
// gate scratch layout: [gate][b][m]
__device__ float g_gates[NG * B_ * M_];
__device__ float g_htilde[B_ * M_];

// ---------------------------------------------------------------------------
// Kernel 1: fused 6-gate GEMM  out[g,b,n] = act_g( x[b,:] . W_g[n,:] + bias_g[n] )
// Tile: BM=32 (batch) x BN=64 (cols) x BK=32.  grid = (96, 2) = 192 blocks
// (all resident: 2 blocks/SM on 148 SMs). 256 threads, 2x4 microtile.
// smem stored k-major so the inner loop is LDS.64 + LDS.128 + 8 FFMA.
// ---------------------------------------------------------------------------
#define XS_STRIDE 34   // even -> 8B alignment for float2 reads, bank-spread stores
#define WS_STRIDE 68   // multiple of 4 -> 16B alignment for float4 reads

__global__ __launch_bounds__(256)
void gates_gemm(const float* __restrict__ x,
                const float* __restrict__ Wq, const float* __restrict__ bq,
                const float* __restrict__ Wk, const float* __restrict__ bk,
                const float* __restrict__ Wv, const float* __restrict__ bv,
                const float* __restrict__ Wi, const float* __restrict__ bi,
                const float* __restrict__ Wf, const float* __restrict__ bf,
                const float* __restrict__ Wo, const float* __restrict__ bo)
{
    const int n_global0 = blockIdx.x * 64;          // [0, 6144)
    const int gate      = n_global0 >> 10;          // 0..5
    const int n_local0  = n_global0 & (M_ - 1);     // within-gate column base
    const int b0        = blockIdx.y * 32;          // batch base

    const float* W; const float* bias;
    switch (gate) {
        case 0: W = Wq; bias = bq; break;
        case 1: W = Wk; bias = bk; break;
        case 2: W = Wv; bias = bv; break;
        case 3: W = Wi; bias = bi; break;
        case 4: W = Wf; bias = bf; break;
        default: W = Wo; bias = bo; break;
    }

    __shared__ float Xs[32][XS_STRIDE];   // [k][b]
    __shared__ float Ws[32][WS_STRIDE];   // [k][n]

    const int tid = threadIdx.x;
    const int tx = tid & 15;       // n direction: 16 groups x 4 cols
    const int ty = tid >> 4;       // b direction: 16 groups x 2 rows

    // global-load indices (transposing into smem)
    const int xb = tid >> 3;       // 0..31  (batch row within tile)
    const int xk = (tid & 7) * 4;  // 0,4,...,28

    float acc[2][4];
    #pragma unroll
    for (int r = 0; r < 2; r++)
        #pragma unroll
        for (int c = 0; c < 4; c++) acc[r][c] = 0.f;

    for (int k0 = 0; k0 < IN_; k0 += 32) {
        // X tile: 32b x 32k = 256 float4, one per thread, coalesced on k
        {
            float4 v = *(const float4*)&x[(b0 + xb) * IN_ + k0 + xk];
            Xs[xk + 0][xb] = v.x;
            Xs[xk + 1][xb] = v.y;
            Xs[xk + 2][xb] = v.z;
            Xs[xk + 3][xb] = v.w;
        }
        // W tile: 64n x 32k = 512 float4, two per thread
        #pragma unroll
        for (int i = 0; i < 2; i++) {
            int idx = tid + i * 256;
            int n  = idx >> 3;
            int kc = (idx & 7) * 4;
            float4 v = *(const float4*)&W[(n_local0 + n) * IN_ + k0 + kc];
            Ws[kc + 0][n] = v.x;
            Ws[kc + 1][n] = v.y;
            Ws[kc + 2][n] = v.z;
            Ws[kc + 3][n] = v.w;
        }
        __syncthreads();

        #pragma unroll
        for (int kk = 0; kk < 32; kk++) {
            float2 a  = *(const float2*)&Xs[kk][ty * 2];
            float4 bb = *(const float4*)&Ws[kk][tx * 4];
            acc[0][0] = fmaf(a.x, bb.x, acc[0][0]);
            acc[0][1] = fmaf(a.x, bb.y, acc[0][1]);
            acc[0][2] = fmaf(a.x, bb.z, acc[0][2]);
            acc[0][3] = fmaf(a.x, bb.w, acc[0][3]);
            acc[1][0] = fmaf(a.y, bb.x, acc[1][0]);
            acc[1][1] = fmaf(a.y, bb.y, acc[1][1]);
            acc[1][2] = fmaf(a.y, bb.z, acc[1][2]);
            acc[1][3] = fmaf(a.y, bb.w, acc[1][3]);
        }
        __syncthreads();
    }

    // epilogue: bias + activation, write to scratch
    float* out = g_gates + gate * (B_ * M_);
    #pragma unroll
    for (int c = 0; c < 4; c++) {
        int n = n_local0 + tx * 4 + c;
        float bv_ = bias[n];
        #pragma unroll
        for (int r = 0; r < 2; r++) {
            int b = b0 + ty * 2 + r;
            float v = acc[r][c] + bv_;
            if (gate == 1)      v *= 0.03125f;                 // 1/sqrt(1024)
            else if (gate == 3) v = __expf(v);                 // i: exp
            else if (gate >= 4) v = 1.f / (1.f + __expf(-v));  // f,o: sigmoid
            out[b * M_ + n] = v;
        }
    }
}

// ---------------------------------------------------------------------------
// Kernel 2: C_t[b,m,:] = f[b,m]*C_prev[b,m,:] + (i*v)[b,m]*k[b,:]
//           h_tilde[b,m] = C_t[b,m,:] . q[b,:]     (fused, warp-reduced)
// grid = (16, 64): blockIdx.y = batch, blockIdx.x = 64-row chunk.
// 256 threads = 8 warps; warp owns one row per iteration (8 iterations).
// Streaming (__ldcs/__stcs) for the 537MB C stream; dual dot accumulators.
// ---------------------------------------------------------------------------
__global__ __launch_bounds__(256)
void update_C(const float* __restrict__ Cprev, float* __restrict__ Cout)
{
    const int b = blockIdx.y;
    __shared__ float sk[M_];
    __shared__ float sq[M_];

    const float* gq = g_gates + 0 * (B_ * M_) + b * M_;
    const float* gk = g_gates + 1 * (B_ * M_) + b * M_;
    // stage k and q in smem (256 float4 each, one per thread)
    ((float4*)sk)[threadIdx.x] = ((const float4*)gk)[threadIdx.x];
    ((float4*)sq)[threadIdx.x] = ((const float4*)gq)[threadIdx.x];
    __syncthreads();

    const int warp = threadIdx.x >> 5;
    const int lane = threadIdx.x & 31;
    const float* gv = g_gates + 2 * (B_ * M_) + b * M_;
    const float* gi = g_gates + 3 * (B_ * M_) + b * M_;
    const float* gf = g_gates + 4 * (B_ * M_) + b * M_;

    #pragma unroll
    for (int r = 0; r < 8; r++) {
        const int m = blockIdx.x * 64 + r * 8 + warp;
        const float fm = gf[m];
        const float cm = gi[m] * gv[m];

        const float4* cp = (const float4*)(Cprev + ((size_t)b * M_ + m) * M_);
        float4*       co = (float4*)(Cout  + ((size_t)b * M_ + m) * M_);

        float dot0 = 0.f, dot1 = 0.f;
        #pragma unroll
        for (int it = 0; it < 8; it += 2) {
            const int na = it * 32 + lane;
            const int nb = na + 32;
            float4 c0 = __ldcs(cp + na);
            float4 c1 = __ldcs(cp + nb);
            float4 k0 = ((const float4*)sk)[na];
            float4 k1 = ((const float4*)sk)[nb];
            float4 q0 = ((const float4*)sq)[na];
            float4 q1 = ((const float4*)sq)[nb];
            float4 o0, o1;
            o0.x = fmaf(fm, c0.x, cm * k0.x);
            o0.y = fmaf(fm, c0.y, cm * k0.y);
            o0.z = fmaf(fm, c0.z, cm * k0.z);
            o0.w = fmaf(fm, c0.w, cm * k0.w);
            o1.x = fmaf(fm, c1.x, cm * k1.x);
            o1.y = fmaf(fm, c1.y, cm * k1.y);
            o1.z = fmaf(fm, c1.z, cm * k1.z);
            o1.w = fmaf(fm, c1.w, cm * k1.w);
            __stcs(co + na, o0);
            __stcs(co + nb, o1);
            dot0 = fmaf(o0.x, q0.x, dot0);
            dot0 = fmaf(o0.y, q0.y, dot0);
            dot0 = fmaf(o0.z, q0.z, dot0);
            dot0 = fmaf(o0.w, q0.w, dot0);
            dot1 = fmaf(o1.x, q1.x, dot1);
            dot1 = fmaf(o1.y, q1.y, dot1);
            dot1 = fmaf(o1.z, q1.z, dot1);
            dot1 = fmaf(o1.w, q1.w, dot1);
        }
        float dot = dot0 + dot1;
        #pragma unroll
        for (int off = 16; off; off >>= 1)
            dot += __shfl_xor_sync(0xffffffffu, dot, off);
        if (lane == 0) g_htilde[b * M_ + m] = dot;
    }
}

// ---------------------------------------------------------------------------
// Kernel 3: n_t = f*n_prev + i*k ; denom = max(n_t.q, 1) ; h_t = o*h_tilde/denom
// One block per batch, 256 threads, 4 elements each.
// ---------------------------------------------------------------------------
__global__ __launch_bounds__(256)
void finalize(const float* __restrict__ nprev,
              float* __restrict__ out_h, float* __restrict__ out_n)
{
    const int b   = blockIdx.x;
    const int tid = threadIdx.x;

    const float* gq = g_gates + 0 * (B_ * M_) + b * M_;
    const float* gk = g_gates + 1 * (B_ * M_) + b * M_;
    const float* gi = g_gates + 3 * (B_ * M_) + b * M_;
    const float* gf = g_gates + 4 * (B_ * M_) + b * M_;
    const float* go = g_gates + 5 * (B_ * M_) + b * M_;

    float part = 0.f;
    #pragma unroll
    for (int r = 0; r < 4; r++) {
        int j = tid + r * 256;
        float n = fmaf(gf[j], nprev[b * M_ + j], gi[j] * gk[j]);
        out_n[b * M_ + j] = n;
        part = fmaf(n, gq[j], part);
    }

    __shared__ float red[256];
    red[tid] = part;
    __syncthreads();
    #pragma unroll
    for (int s = 128; s > 0; s >>= 1) {
        if (tid < s) red[tid] += red[tid + s];
        __syncthreads();
    }
    const float denom = fmaxf(red[0], 1.0f);
    const float inv   = 1.0f / denom;

    #pragma unroll
    for (int r = 0; r < 4; r++) {
        int j = tid + r * 256;
        out_h[b * M_ + j] = go[j] * g_htilde[b * M_ + j] * inv;
    }
}

// ---------------------------------------------------------------------------
// Launch. Inputs (metadata order):
// 0 x, 1 h_prev, 2 c_prev, 3 C_prev, 4 n_prev, 5 m_prev,
// 6 Wq, 7 bq, 8 Wk, 9 bk, 10 Wv, 11 bv, 12 Wi, 13 bi, 14 Wf, 15 bf, 16 Wo, 17 bo
// Output: concat(h_t [64*1024], C_t [64*1024*1024], n_t [64*1024])
// ---------------------------------------------------------------------------
extern "C" void kernel_launch(void* const* d_in, const int* in_sizes, int n_in,
                              void* d_out, int out_size)
{
    const float* x     = (const float*)d_in[0];
    const float* Cprev = (const float*)d_in[3];
    const float* nprev = (const float*)d_in[4];

    const float* Wq = (const float*)d_in[6];  const float* bq = (const float*)d_in[7];
    const float* Wk = (const float*)d_in[8];  const float* bk = (const float*)d_in[9];
    const float* Wv = (const float*)d_in[10]; const float* bv = (const float*)d_in[11];
    const float* Wi = (const float*)d_in[12]; const float* bi = (const float*)d_in[13];
    const float* Wf = (const float*)d_in[14]; const float* bf = (const float*)d_in[15];
    const float* Wo = (const float*)d_in[16]; const float* bo = (const float*)d_in[17];

    float* out   = (float*)d_out;
    float* out_h = out;                                    // [64*1024]
    float* out_C = out + (size_t)B_ * M_;                  // [64*1024*1024]
    float* out_n = out + (size_t)B_ * M_ + (size_t)B_ * M_ * M_;

    dim3 grid1(96, 2);
    gates_gemm<<<grid1, 256>>>(x, Wq, bq, Wk, bk, Wv, bv, Wi, bi, Wf, bf, Wo, bo);

    dim3 grid2(16, 64);
    update_C<<<grid2, 256>>>(Cprev, out_C);

    finalize<<<B_, 256>>>(nprev, out_h, out_n);
}

// round 3
// speedup vs baseline: 1.1913x; 1.0853x over previous
#include <cuda_runtime.h>
#include <math.h>

// Problem constants
#define B_   64
#define IN_  512
#define M_   1024
#define NG   6          // q,k,v,i,f,o
// gate scratch layout: [gate][b][m]
__device__ float g_gates[NG * B_ * M_];
__device__ float g_htilde[B_ * M_];

// ---------------------------------------------------------------------------
// Kernel 1: fused 6-gate GEMM  out[g,b,n] = act_g( x[b,:] . W_g[n,:] + bias_g[n] )
// Tile: BM=64 (all batches) x BN=64 x BK=32, 256 threads, 4x4 microtile,
// double-buffered smem with register prefetch. grid = 96 blocks (1/SM, all
// resident). Inner loop: 2x LDS.128 + 16 FFMA per kk.
// smem is k-major: Xs[k][b], Ws[k][n], stride 68 (16B-aligned rows).
// ---------------------------------------------------------------------------
#define SST 68

__global__ __launch_bounds__(256)
void gates_gemm(const float* __restrict__ x,
                const float* __restrict__ Wq, const float* __restrict__ bq,
                const float* __restrict__ Wk, const float* __restrict__ bk,
                const float* __restrict__ Wv, const float* __restrict__ bv,
                const float* __restrict__ Wi, const float* __restrict__ bi,
                const float* __restrict__ Wf, const float* __restrict__ bf,
                const float* __restrict__ Wo, const float* __restrict__ bo)
{
    const int n_global0 = blockIdx.x * 64;          // [0, 6144)
    const int gate      = n_global0 >> 10;          // 0..5
    const int n_local0  = n_global0 & (M_ - 1);     // within-gate column base

    const float* W; const float* bias;
    switch (gate) {
        case 0: W = Wq; bias = bq; break;
        case 1: W = Wk; bias = bk; break;
        case 2: W = Wv; bias = bv; break;
        case 3: W = Wi; bias = bi; break;
        case 4: W = Wf; bias = bf; break;
        default: W = Wo; bias = bo; break;
    }

    __shared__ float Xs[2][32][SST];   // [buf][k][b]
    __shared__ float Ws[2][32][SST];   // [buf][k][n]

    const int tid = threadIdx.x;
    const int tx = tid & 15;       // n direction: 16 groups x 4
    const int ty = tid >> 4;       // b direction: 16 groups x 4

    // global-load mapping: thread owns row lr, 8 consecutive k at lk
    const int lr = tid >> 2;         // 0..63
    const int lk = (tid & 3) * 8;    // 0,8,16,24

    const float* xg = x + lr * IN_ + lk;
    const float* wg = W + (n_local0 + lr) * IN_ + lk;

    float4 xr0, xr1, wr0, wr1;

    // prefetch tile 0
    xr0 = *(const float4*)(xg + 0);
    xr1 = *(const float4*)(xg + 4);
    wr0 = *(const float4*)(wg + 0);
    wr1 = *(const float4*)(wg + 4);

    float acc[4][4];
    #pragma unroll
    for (int r = 0; r < 4; r++)
        #pragma unroll
        for (int c = 0; c < 4; c++) acc[r][c] = 0.f;

    int buf = 0;
    // store tile 0
    {
        Xs[0][lk + 0][lr] = xr0.x; Xs[0][lk + 1][lr] = xr0.y;
        Xs[0][lk + 2][lr] = xr0.z; Xs[0][lk + 3][lr] = xr0.w;
        Xs[0][lk + 4][lr] = xr1.x; Xs[0][lk + 5][lr] = xr1.y;
        Xs[0][lk + 6][lr] = xr1.z; Xs[0][lk + 7][lr] = xr1.w;
        Ws[0][lk + 0][lr] = wr0.x; Ws[0][lk + 1][lr] = wr0.y;
        Ws[0][lk + 2][lr] = wr0.z; Ws[0][lk + 3][lr] = wr0.w;
        Ws[0][lk + 4][lr] = wr1.x; Ws[0][lk + 5][lr] = wr1.y;
        Ws[0][lk + 6][lr] = wr1.z; Ws[0][lk + 7][lr] = wr1.w;
    }
    __syncthreads();

    #pragma unroll 1
    for (int it = 0; it < IN_ / 32; it++) {
        // prefetch next tile into registers (overlaps with compute below)
        if (it < IN_ / 32 - 1) {
            const int k0 = (it + 1) * 32;
            xr0 = *(const float4*)(xg + k0 + 0);
            xr1 = *(const float4*)(xg + k0 + 4);
            wr0 = *(const float4*)(wg + k0 + 0);
            wr1 = *(const float4*)(wg + k0 + 4);
        }

        // compute on current buffer
        #pragma unroll
        for (int kk = 0; kk < 32; kk++) {
            float4 a  = *(const float4*)&Xs[buf][kk][ty * 4];
            float4 bb = *(const float4*)&Ws[buf][kk][tx * 4];
            acc[0][0] = fmaf(a.x, bb.x, acc[0][0]);
            acc[0][1] = fmaf(a.x, bb.y, acc[0][1]);
            acc[0][2] = fmaf(a.x, bb.z, acc[0][2]);
            acc[0][3] = fmaf(a.x, bb.w, acc[0][3]);
            acc[1][0] = fmaf(a.y, bb.x, acc[1][0]);
            acc[1][1] = fmaf(a.y, bb.y, acc[1][1]);
            acc[1][2] = fmaf(a.y, bb.z, acc[1][2]);
            acc[1][3] = fmaf(a.y, bb.w, acc[1][3]);
            acc[2][0] = fmaf(a.z, bb.x, acc[2][0]);
            acc[2][1] = fmaf(a.z, bb.y, acc[2][1]);
            acc[2][2] = fmaf(a.z, bb.z, acc[2][2]);
            acc[2][3] = fmaf(a.z, bb.w, acc[2][3]);
            acc[3][0] = fmaf(a.w, bb.x, acc[3][0]);
            acc[3][1] = fmaf(a.w, bb.y, acc[3][1]);
            acc[3][2] = fmaf(a.w, bb.z, acc[3][2]);
            acc[3][3] = fmaf(a.w, bb.w, acc[3][3]);
        }

        if (it < IN_ / 32 - 1) {
            const int nb = buf ^ 1;
            Xs[nb][lk + 0][lr] = xr0.x; Xs[nb][lk + 1][lr] = xr0.y;
            Xs[nb][lk + 2][lr] = xr0.z; Xs[nb][lk + 3][lr] = xr0.w;
            Xs[nb][lk + 4][lr] = xr1.x; Xs[nb][lk + 5][lr] = xr1.y;
            Xs[nb][lk + 6][lr] = xr1.z; Xs[nb][lk + 7][lr] = xr1.w;
            Ws[nb][lk + 0][lr] = wr0.x; Ws[nb][lk + 1][lr] = wr0.y;
            Ws[nb][lk + 2][lr] = wr0.z; Ws[nb][lk + 3][lr] = wr0.w;
            Ws[nb][lk + 4][lr] = wr1.x; Ws[nb][lk + 5][lr] = wr1.y;
            Ws[nb][lk + 6][lr] = wr1.z; Ws[nb][lk + 7][lr] = wr1.w;
            __syncthreads();
            buf = nb;
        }
    }

    // epilogue: bias + activation, vectorized write (float4 over n)
    float* out = g_gates + gate * (B_ * M_);
    const int n = n_local0 + tx * 4;
    const float4 bv4 = *(const float4*)&bias[n];
    #pragma unroll
    for (int r = 0; r < 4; r++) {
        const int b = ty * 4 + r;
        float4 v;
        v.x = acc[r][0] + bv4.x;
        v.y = acc[r][1] + bv4.y;
        v.z = acc[r][2] + bv4.z;
        v.w = acc[r][3] + bv4.w;
        if (gate == 1) {
            v.x *= 0.03125f; v.y *= 0.03125f; v.z *= 0.03125f; v.w *= 0.03125f;
        } else if (gate == 3) {
            v.x = __expf(v.x); v.y = __expf(v.y); v.z = __expf(v.z); v.w = __expf(v.w);
        } else if (gate >= 4) {
            v.x = 1.f / (1.f + __expf(-v.x));
            v.y = 1.f / (1.f + __expf(-v.y));
            v.z = 1.f / (1.f + __expf(-v.z));
            v.w = 1.f / (1.f + __expf(-v.w));
        }
        *(float4*)&out[b * M_ + n] = v;
    }
}

// ---------------------------------------------------------------------------
// Kernel 2: C_t[b,m,:] = f[b,m]*C_prev[b,m,:] + (i*v)[b,m]*k[b,:]
//           h_tilde[b,m] = C_t[b,m,:] . q[b,:]     (fused, warp-reduced)
// grid = (16, 64): blockIdx.y = batch, blockIdx.x = 64-row chunk.
// 8 warps, warp owns one row per iteration. All 8 row-loads issued upfront
// (MLP=8 per warp), streaming loads/stores so the 537MB stream bypasses L2
// allocation.
// ---------------------------------------------------------------------------
__global__ __launch_bounds__(256)
void update_C(const float* __restrict__ Cprev, float* __restrict__ Cout)
{
    const int b = blockIdx.y;
    __shared__ float sk[M_];
    __shared__ float sq[M_];

    const float* gq = g_gates + 0 * (B_ * M_) + b * M_;
    const float* gk = g_gates + 1 * (B_ * M_) + b * M_;
    ((float4*)sk)[threadIdx.x] = ((const float4*)gk)[threadIdx.x];
    ((float4*)sq)[threadIdx.x] = ((const float4*)gq)[threadIdx.x];
    __syncthreads();

    const int warp = threadIdx.x >> 5;
    const int lane = threadIdx.x & 31;
    const float* gv = g_gates + 2 * (B_ * M_) + b * M_;
    const float* gi = g_gates + 3 * (B_ * M_) + b * M_;
    const float* gf = g_gates + 4 * (B_ * M_) + b * M_;

    const float4* sk4 = (const float4*)sk;
    const float4* sq4 = (const float4*)sq;

    #pragma unroll
    for (int r = 0; r < 8; r++) {
        const int m = blockIdx.x * 64 + r * 8 + warp;
        const float fm = gf[m];
        const float cm = gi[m] * gv[m];

        const float4* cp = (const float4*)(Cprev + ((size_t)b * M_ + m) * M_);
        float4*       co = (float4*)(Cout  + ((size_t)b * M_ + m) * M_);

        // issue the whole row's loads first: MLP = 8
        float4 c[8];
        #pragma unroll
        for (int j = 0; j < 8; j++)
            c[j] = __ldcs(cp + j * 32 + lane);

        float dot0 = 0.f, dot1 = 0.f;
        #pragma unroll
        for (int j = 0; j < 8; j++) {
            const int n4 = j * 32 + lane;
            float4 kk = sk4[n4];
            float4 qq = sq4[n4];
            float4 o;
            o.x = fmaf(fm, c[j].x, cm * kk.x);
            o.y = fmaf(fm, c[j].y, cm * kk.y);
            o.z = fmaf(fm, c[j].z, cm * kk.z);
            o.w = fmaf(fm, c[j].w, cm * kk.w);
            __stcs(co + n4, o);
            if (j & 1) {
                dot1 = fmaf(o.x, qq.x, dot1);
                dot1 = fmaf(o.y, qq.y, dot1);
                dot1 = fmaf(o.z, qq.z, dot1);
                dot1 = fmaf(o.w, qq.w, dot1);
            } else {
                dot0 = fmaf(o.x, qq.x, dot0);
                dot0 = fmaf(o.y, qq.y, dot0);
                dot0 = fmaf(o.z, qq.z, dot0);
                dot0 = fmaf(o.w, qq.w, dot0);
            }
        }
        float dot = dot0 + dot1;
        #pragma unroll
        for (int off = 16; off; off >>= 1)
            dot += __shfl_xor_sync(0xffffffffu, dot, off);
        if (lane == 0) g_htilde[b * M_ + m] = dot;
    }
}

// ---------------------------------------------------------------------------
// Kernel 3: n_t = f*n_prev + i*k ; denom = max(n_t.q, 1) ; h_t = o*h_tilde/denom
// ---------------------------------------------------------------------------
__global__ __launch_bounds__(256)
void finalize(const float* __restrict__ nprev,
              float* __restrict__ out_h, float* __restrict__ out_n)
{
    const int b   = blockIdx.x;
    const int tid = threadIdx.x;

    const float* gq = g_gates + 0 * (B_ * M_) + b * M_;
    const float* gk = g_gates + 1 * (B_ * M_) + b * M_;
    const float* gi = g_gates + 3 * (B_ * M_) + b * M_;
    const float* gf = g_gates + 4 * (B_ * M_) + b * M_;
    const float* go = g_gates + 5 * (B_ * M_) + b * M_;

    float part = 0.f;
    #pragma unroll
    for (int r = 0; r < 4; r++) {
        int j = tid + r * 256;
        float n = fmaf(gf[j], nprev[b * M_ + j], gi[j] * gk[j]);
        out_n[b * M_ + j] = n;
        part = fmaf(n, gq[j], part);
    }

    __shared__ float red[256];
    red[tid] = part;
    __syncthreads();
    #pragma unroll
    for (int s = 128; s > 0; s >>= 1) {
        if (tid < s) red[tid] += red[tid + s];
        __syncthreads();
    }
    const float denom = fmaxf(red[0], 1.0f);
    const float inv   = 1.0f / denom;

    #pragma unroll
    for (int r = 0; r < 4; r++) {
        int j = tid + r * 256;
        out_h[b * M_ + j] = go[j] * g_htilde[b * M_ + j] * inv;
    }
}

// ---------------------------------------------------------------------------
// Launch. Inputs (metadata order):
// 0 x, 1 h_prev, 2 c_prev, 3 C_prev, 4 n_prev, 5 m_prev,
// 6 Wq, 7 bq, 8 Wk, 9 bk, 10 Wv, 11 bv, 12 Wi, 13 bi, 14 Wf, 15 bf, 16 Wo, 17 bo
// Output: concat(h_t [64*1024], C_t [64*1024*1024], n_t [64*1024])
// ---------------------------------------------------------------------------
extern "C" void kernel_launch(void* const* d_in, const int* in_sizes, int n_in,
                              void* d_out, int out_size)
{
    const float* x     = (const float*)d_in[0];
    const float* Cprev = (const float*)d_in[3];
    const float* nprev = (const float*)d_in[4];

    const float* Wq = (const float*)d_in[6];  const float* bq = (const float*)d_in[7];
    const float* Wk = (const float*)d_in[8];  const float* bk = (const float*)d_in[9];
    const float* Wv = (const float*)d_in[10]; const float* bv = (const float*)d_in[11];
    const float* Wi = (const float*)d_in[12]; const float* bi = (const float*)d_in[13];
    const float* Wf = (const float*)d_in[14]; const float* bf = (const float*)d_in[15];
    const float* Wo = (const float*)d_in[16]; const float* bo = (const float*)d_in[17];

    float* out   = (float*)d_out;
    float* out_h = out;                                    // [64*1024]
    float* out_C = out + (size_t)B_ * M_;                  // [64*1024*1024]
    float* out_n = out + (size_t)B_ * M_ + (size_t)B_ * M_ * M_;

    gates_gemm<<<96, 256>>>(x, Wq, bq, Wk, bk, Wv, bv, Wi, bi, Wf, bf, Wo, bo);

    dim3 grid2(16, 64);
    update_C<<<grid2, 256>>>(Cprev, out_C);

    finalize<<<B_, 256>>>(nprev, out_h, out_n);
}